// round 2
// baseline (speedup 1.0000x reference)
#include <cuda_runtime.h>

#define Bsz 4
#define Tn 2048
#define Cn 1024
#define Hn 16
#define Dn 64
#define NTOK (Bsz*Tn)   // 8192

// Scratch (device globals: allocation-free)
__device__ float g_q[Bsz*Hn*Tn*Dn];
__device__ float g_k[Bsz*Hn*Tn*Dn];
__device__ float g_v[Bsz*Hn*Tn*Dn];
__device__ float g_y[Bsz*Tn*Cn];

// ---------------------------------------------------------------------------
// GEMM1: qkv = x[8192,1024] @ W_attn[1024,3072] + b_attn
// scatter into g_q/g_k/g_v with layout [B,H,T,D]; q scaled by 1/sqrt(D)
// 128x128 block tile, K-step 8, 256 threads, 8x8 per thread.
// ---------------------------------------------------------------------------
__global__ __launch_bounds__(256) void gemm_qkv_kernel(
    const float* __restrict__ X, const float* __restrict__ W,
    const float* __restrict__ bias)
{
    __shared__ float As[8][128];
    __shared__ float Bs[8][128];
    const int tid = threadIdx.x;
    const int tx = tid & 15, ty = tid >> 4;
    const int m0 = blockIdx.y * 128;
    const int n0 = blockIdx.x * 128;

    const int arow = tid >> 1, akq = (tid & 1) * 4;
    const int bk = tid >> 5, bnq = (tid & 31) * 4;

    float acc[8][8];
#pragma unroll
    for (int i = 0; i < 8; i++)
#pragma unroll
        for (int j = 0; j < 8; j++) acc[i][j] = 0.0f;

    for (int k0 = 0; k0 < 1024; k0 += 8) {
        __syncthreads();
        float4 av = *(const float4*)(X + (size_t)(m0 + arow) * 1024 + k0 + akq);
        As[akq + 0][arow] = av.x;
        As[akq + 1][arow] = av.y;
        As[akq + 2][arow] = av.z;
        As[akq + 3][arow] = av.w;
        float4 bv = *(const float4*)(W + (size_t)(k0 + bk) * 3072 + n0 + bnq);
        *(float4*)&Bs[bk][bnq] = bv;
        __syncthreads();
#pragma unroll
        for (int kk = 0; kk < 8; kk++) {
            float4 a0 = *(float4*)&As[kk][ty * 4];
            float4 a1 = *(float4*)&As[kk][64 + ty * 4];
            float4 b0 = *(float4*)&Bs[kk][tx * 4];
            float4 b1 = *(float4*)&Bs[kk][64 + tx * 4];
            float af[8] = {a0.x, a0.y, a0.z, a0.w, a1.x, a1.y, a1.z, a1.w};
            float bf[8] = {b0.x, b0.y, b0.z, b0.w, b1.x, b1.y, b1.z, b1.w};
#pragma unroll
            for (int i = 0; i < 8; i++)
#pragma unroll
                for (int j = 0; j < 8; j++) acc[i][j] += af[i] * bf[j];
        }
    }

    // Epilogue: scatter to q/k/v [B,H,T,D]. A 128-col block lies entirely in
    // one of q/k/v (3072/128=24 blocks, 8 per segment) and spans 2 heads.
    const int seg = n0 >> 10;             // 0=q 1=k 2=v
    float* dst = (seg == 0) ? g_q : (seg == 1) ? g_k : g_v;
    const float scale = (seg == 0) ? 0.125f : 1.0f;  // 1/sqrt(64)
    const int h0 = (n0 & 1023) >> 6;
    const int d = tx * 4;
#pragma unroll
    for (int jg = 0; jg < 2; jg++) {
        const int h = h0 + jg;
        float4 bb = *(const float4*)(bias + n0 + jg * 64 + d);
#pragma unroll
        for (int ig = 0; ig < 2; ig++) {
#pragma unroll
            for (int i = 0; i < 4; i++) {
                const int m = m0 + ig * 64 + ty * 4 + i;
                const int b = m >> 11;       // /T
                const int t = m & 2047;      // %T
                const int ai = ig * 4 + i, aj = jg * 4;
                float4 o;
                o.x = (acc[ai][aj + 0] + bb.x) * scale;
                o.y = (acc[ai][aj + 1] + bb.y) * scale;
                o.z = (acc[ai][aj + 2] + bb.z) * scale;
                o.w = (acc[ai][aj + 3] + bb.w) * scale;
                *(float4*)(dst + ((size_t)(b * Hn + h) * Tn + t) * Dn + d) = o;
            }
        }
    }
}

// ---------------------------------------------------------------------------
// GEMM2: out = y[8192,1024] @ W_proj[1024,1024] + b_proj
// ---------------------------------------------------------------------------
__global__ __launch_bounds__(256) void gemm_proj_kernel(
    const float* __restrict__ W, const float* __restrict__ bias,
    float* __restrict__ out)
{
    __shared__ float As[8][128];
    __shared__ float Bs[8][128];
    const int tid = threadIdx.x;
    const int tx = tid & 15, ty = tid >> 4;
    const int m0 = blockIdx.y * 128;
    const int n0 = blockIdx.x * 128;

    const int arow = tid >> 1, akq = (tid & 1) * 4;
    const int bk = tid >> 5, bnq = (tid & 31) * 4;

    float acc[8][8];
#pragma unroll
    for (int i = 0; i < 8; i++)
#pragma unroll
        for (int j = 0; j < 8; j++) acc[i][j] = 0.0f;

    for (int k0 = 0; k0 < 1024; k0 += 8) {
        __syncthreads();
        float4 av = *(const float4*)(g_y + (size_t)(m0 + arow) * 1024 + k0 + akq);
        As[akq + 0][arow] = av.x;
        As[akq + 1][arow] = av.y;
        As[akq + 2][arow] = av.z;
        As[akq + 3][arow] = av.w;
        float4 bv = *(const float4*)(W + (size_t)(k0 + bk) * 1024 + n0 + bnq);
        *(float4*)&Bs[bk][bnq] = bv;
        __syncthreads();
#pragma unroll
        for (int kk = 0; kk < 8; kk++) {
            float4 a0 = *(float4*)&As[kk][ty * 4];
            float4 a1 = *(float4*)&As[kk][64 + ty * 4];
            float4 b0 = *(float4*)&Bs[kk][tx * 4];
            float4 b1 = *(float4*)&Bs[kk][64 + tx * 4];
            float af[8] = {a0.x, a0.y, a0.z, a0.w, a1.x, a1.y, a1.z, a1.w};
            float bf[8] = {b0.x, b0.y, b0.z, b0.w, b1.x, b1.y, b1.z, b1.w};
#pragma unroll
            for (int i = 0; i < 8; i++)
#pragma unroll
                for (int j = 0; j < 8; j++) acc[i][j] += af[i] * bf[j];
        }
    }

#pragma unroll
    for (int jg = 0; jg < 2; jg++) {
        const int n = n0 + jg * 64 + tx * 4;
        float4 bb = *(const float4*)(bias + n);
#pragma unroll
        for (int ig = 0; ig < 2; ig++) {
#pragma unroll
            for (int i = 0; i < 4; i++) {
                const int m = m0 + ig * 64 + ty * 4 + i;
                const int ai = ig * 4 + i, aj = jg * 4;
                float4 o;
                o.x = acc[ai][aj + 0] + bb.x;
                o.y = acc[ai][aj + 1] + bb.y;
                o.z = acc[ai][aj + 2] + bb.z;
                o.w = acc[ai][aj + 3] + bb.w;
                *(float4*)(out + (size_t)m * 1024 + n) = o;
            }
        }
    }
}

// ---------------------------------------------------------------------------
// Flash attention: one CTA per (b*h, q-tile of 64 rows). BLOCK_N=64, D=64.
// 256 threads as 16x16; each thread owns a 4(row) x 4(col) fragment.
// Causal: only kt <= qi tiles visited; diagonal tile masked.
// ---------------------------------------------------------------------------
#define SSTR 68  // smem row stride (floats): mult of 4 for float4, !=64 for banks

__global__ __launch_bounds__(256) void attn_kernel()
{
    extern __shared__ float sm[];
    float* Qs = sm;                // [D][SSTR] transposed: Qs[d*SSTR + m]
    float* Ks = Qs + 64 * SSTR;    // [D][SSTR] transposed: Ks[d*SSTR + n]
    float* Vs = Ks + 64 * SSTR;    // [N][SSTR] natural:    Vs[k*SSTR + d]
    float* Ps = Vs + 64 * SSTR;    // [M][SSTR] natural:    Ps[m*SSTR + k]

    const int tid = threadIdx.x;
    const int tx = tid & 15, ty = tid >> 4;
    const int qi = blockIdx.x;
    const int bh = blockIdx.y;

    const float* qg = g_q + (size_t)bh * Tn * Dn + (size_t)qi * 64 * Dn;
    const float* kg = g_k + (size_t)bh * Tn * Dn;
    const float* vg = g_v + (size_t)bh * Tn * Dn;

    // Load Q tile (transposed into smem); 1/sqrt(D) already folded in.
#pragma unroll
    for (int i = 0; i < 4; i++) {
        const int lin = tid + i * 256;   // float4 index, 1024 total
        const int row = lin >> 4;
        const int c4 = (lin & 15) * 4;
        float4 v = *(const float4*)(qg + row * 64 + c4);
        Qs[(c4 + 0) * SSTR + row] = v.x;
        Qs[(c4 + 1) * SSTR + row] = v.y;
        Qs[(c4 + 2) * SSTR + row] = v.z;
        Qs[(c4 + 3) * SSTR + row] = v.w;
    }

    float m_i[4], l_i[4], acc[4][4];
#pragma unroll
    for (int i = 0; i < 4; i++) {
        m_i[i] = -1e30f;
        l_i[i] = 0.0f;
#pragma unroll
        for (int j = 0; j < 4; j++) acc[i][j] = 0.0f;
    }

    const int qrow_base = qi * 64 + ty * 4;

    for (int kt = 0; kt <= qi; kt++) {
        __syncthreads();
        const float* kp = kg + (size_t)kt * 64 * Dn;
        const float* vp = vg + (size_t)kt * 64 * Dn;
#pragma unroll
        for (int i = 0; i < 4; i++) {
            const int lin = tid + i * 256;
            const int row = lin >> 4;
            const int c4 = (lin & 15) * 4;
            float4 kv = *(const float4*)(kp + row * 64 + c4);
            Ks[(c4 + 0) * SSTR + row] = kv.x;
            Ks[(c4 + 1) * SSTR + row] = kv.y;
            Ks[(c4 + 2) * SSTR + row] = kv.z;
            Ks[(c4 + 3) * SSTR + row] = kv.w;
            float4 vv = *(const float4*)(vp + row * 64 + c4);
            *(float4*)&Vs[row * SSTR + c4] = vv;
        }
        __syncthreads();

        // S = Q K^T (q pre-scaled)
        float s[4][4];
#pragma unroll
        for (int i = 0; i < 4; i++)
#pragma unroll
            for (int j = 0; j < 4; j++) s[i][j] = 0.0f;
#pragma unroll 16
        for (int dd = 0; dd < 64; dd++) {
            float4 qf = *(float4*)&Qs[dd * SSTR + ty * 4];
            float4 kf = *(float4*)&Ks[dd * SSTR + tx * 4];
            float qa[4] = {qf.x, qf.y, qf.z, qf.w};
            float ka[4] = {kf.x, kf.y, kf.z, kf.w};
#pragma unroll
            for (int i = 0; i < 4; i++)
#pragma unroll
                for (int j = 0; j < 4; j++) s[i][j] += qa[i] * ka[j];
        }

        if (kt == qi) {  // diagonal tile: causal mask
#pragma unroll
            for (int i = 0; i < 4; i++)
#pragma unroll
                for (int j = 0; j < 4; j++)
                    if (kt * 64 + tx * 4 + j > qrow_base + i) s[i][j] = -1e30f;
        }

        // online softmax update
        float mnew[4];
#pragma unroll
        for (int i = 0; i < 4; i++) {
            float v = fmaxf(fmaxf(s[i][0], s[i][1]), fmaxf(s[i][2], s[i][3]));
#pragma unroll
            for (int off = 1; off < 16; off <<= 1)
                v = fmaxf(v, __shfl_xor_sync(0xffffffffu, v, off));
            mnew[i] = fmaxf(m_i[i], v);
        }
#pragma unroll
        for (int i = 0; i < 4; i++) {
            const float a = __expf(m_i[i] - mnew[i]);
            m_i[i] = mnew[i];
            float r = 0.0f;
#pragma unroll
            for (int j = 0; j < 4; j++) {
                s[i][j] = __expf(s[i][j] - mnew[i]);
                r += s[i][j];
            }
#pragma unroll
            for (int off = 1; off < 16; off <<= 1)
                r += __shfl_xor_sync(0xffffffffu, r, off);
            l_i[i] = l_i[i] * a + r;
#pragma unroll
            for (int j = 0; j < 4; j++) acc[i][j] *= a;
        }

        // stage P (natural layout, conflict-free float4 stores)
#pragma unroll
        for (int i = 0; i < 4; i++)
            *(float4*)&Ps[(ty * 4 + i) * SSTR + tx * 4] =
                make_float4(s[i][0], s[i][1], s[i][2], s[i][3]);
        __syncthreads();

        // O += P @ V
#pragma unroll 16
        for (int k = 0; k < 64; k++) {
            float p0 = Ps[(ty * 4 + 0) * SSTR + k];
            float p1 = Ps[(ty * 4 + 1) * SSTR + k];
            float p2 = Ps[(ty * 4 + 2) * SSTR + k];
            float p3 = Ps[(ty * 4 + 3) * SSTR + k];
            float4 vf = *(float4*)&Vs[k * SSTR + tx * 4];
            acc[0][0] += p0 * vf.x; acc[0][1] += p0 * vf.y; acc[0][2] += p0 * vf.z; acc[0][3] += p0 * vf.w;
            acc[1][0] += p1 * vf.x; acc[1][1] += p1 * vf.y; acc[1][2] += p1 * vf.z; acc[1][3] += p1 * vf.w;
            acc[2][0] += p2 * vf.x; acc[2][1] += p2 * vf.y; acc[2][2] += p2 * vf.z; acc[2][3] += p2 * vf.w;
            acc[3][0] += p3 * vf.x; acc[3][1] += p3 * vf.y; acc[3][2] += p3 * vf.z; acc[3][3] += p3 * vf.w;
        }
    }

    // write y[b, t, h*64+d]
    const int b = bh >> 4, h = bh & 15;
#pragma unroll
    for (int i = 0; i < 4; i++) {
        const float inv = 1.0f / l_i[i];
        const int t = qi * 64 + ty * 4 + i;
        float4 o = make_float4(acc[i][0] * inv, acc[i][1] * inv,
                               acc[i][2] * inv, acc[i][3] * inv);
        *(float4*)(g_y + ((size_t)(b * Tn + t)) * Cn + h * 64 + tx * 4) = o;
    }
}

// ---------------------------------------------------------------------------
extern "C" void kernel_launch(void* const* d_in, const int* in_sizes, int n_in,
                              void* d_out, int out_size)
{
    const float* x      = (const float*)d_in[0];
    const float* W_attn = (const float*)d_in[1];
    const float* b_attn = (const float*)d_in[2];
    const float* W_proj = (const float*)d_in[3];
    const float* b_proj = (const float*)d_in[4];
    float* out = (float*)d_out;

    dim3 blk(256);
    gemm_qkv_kernel<<<dim3(24, 64), blk>>>(x, W_attn, b_attn);

    const int smem = 4 * 64 * SSTR * (int)sizeof(float);  // 69632 B
    cudaFuncSetAttribute(attn_kernel,
                         cudaFuncAttributeMaxDynamicSharedMemorySize, smem);
    attn_kernel<<<dim3(Tn / 64, Bsz * Hn), blk, smem>>>();

    gemm_proj_kernel<<<dim3(8, 64), blk>>>(W_proj, b_proj, out);
}